// round 14
// baseline (speedup 1.0000x reference)
#include <cuda_runtime.h>

typedef unsigned long long ull;

#define N_NODES 2048
#define NODE_DIM 128
#define HIDDEN 64

// Scratch (no allocation allowed — device globals)
// Channel-permuted, pre-scaled staging: slot s holds channel h with slotofh[h]=s,
// value scaled by |c_h|/2. Slots 0..P-1 = positive c, P..63 = negative c.
// Layout: float[(slot>>1)][node][slot&1]  -> loads as ull pairs [pair][node].
__device__ __align__(16) float g_AT[32 * N_NODES * 2];
__device__ __align__(16) float g_BT[32 * N_NODES * 2];
__device__ __align__(16) float g_Sa[N_NODES];            // b2 + sum_h (c/2) a_ih
__device__ __align__(16) float g_Sb[N_NODES];            // sum_h (c/2) b_jh
__device__ int g_slotofh[64];
__device__ int g_PB;     // number of pure-positive pairs
__device__ int g_MX;     // 1 if a mixed boundary pair exists (P odd)

// ---------------------------------------------------------------------------
// Setup: sign-sort channel permutation. 64 threads: parallel flag load,
// thread 0 serial prefix scan over smem (64 iters, trivial).
// ---------------------------------------------------------------------------
__global__ void setup(const float* __restrict__ W2)
{
    __shared__ int pos[64];
    const int t = threadIdx.x;
    if (t < 64) pos[t] = (W2[t] >= 0.0f) ? 1 : 0;
    __syncthreads();
    if (t == 0) {
        int P = 0;
        for (int h = 0; h < 64; h++) P += pos[h];
        int ip = 0, in = P;
        for (int h = 0; h < 64; h++)
            g_slotofh[h] = pos[h] ? ip++ : in++;
        g_PB = P >> 1;
        g_MX = P & 1;
    }
}

// ---------------------------------------------------------------------------
// Fused prep: per block of 16 nodes:
//   phase A: H = X @ W_enc + b_enc           (into smem Hs)
//   phase B: [a|b] = H @ [Wa|Wb] (+b1 on a), scale each channel by |c_h|/2,
//            scatter-store into sign-permuted slots of g_AT/g_BT;
//            Sa/Sb separable sums via smem reduce.
// ---------------------------------------------------------------------------
__global__ __launch_bounds__(256, 2) void prep(const float* __restrict__ X,
                                               const float* __restrict__ W_enc,
                                               const float* __restrict__ b_enc,
                                               const float* __restrict__ W1,
                                               const float* __restrict__ b1,
                                               const float* __restrict__ W2,
                                               const float* __restrict__ b2)
{
    __shared__ union {
        struct {
            float Xs[16][129];          // stride 129 -> conflict-free
            ull   We[NODE_DIM][32];     // W_enc col-pairs
        } A;
        ull W1s[128][32];               // phase B: full W1 as col-pairs
    } u;
    __shared__ float Hs[16][65];        // H tile, stride 65
    __shared__ ull   bes[32];           // b_enc pairs
    __shared__ ull   b1s[32];           // b1 pairs
    __shared__ float c2s[64];           // c/2 (signed)
    __shared__ float cab[64];           // |c|/2 per channel
    __shared__ int   sml[64];           // slotofh
    __shared__ float pa[16][17], pb[16][17];

    const int t  = threadIdx.x;
    const int n0 = blockIdx.x * 16;
    const int tx = t & 15;              // node lane
    const int ty = t >> 4;              // 0..15

    // ---- phase A fills ----
    for (int idx = t; idx < NODE_DIM * 32; idx += 256) {
        int k = idx >> 5, p = idx & 31;
        u.A.We[k][p] = *(const ull*)&W_enc[k * HIDDEN + 2 * p];
    }
    for (int idx = t; idx < 16 * NODE_DIM; idx += 256) {
        int n = idx >> 7, d = idx & 127;
        u.A.Xs[n][d] = X[(n0 + n) * NODE_DIM + d];
    }
    if (t < 32) bes[t] = *(const ull*)&b_enc[2 * t];
    else if (t >= 64 && t < 96) b1s[t - 64] = *(const ull*)&b1[2 * (t - 64)];
    if (t >= 128 && t < 192) {
        int h = t - 128;
        float w = W2[h];
        c2s[h] = 0.5f * w;
        cab[h] = 0.5f * fabsf(w);
        sml[h] = g_slotofh[h];
    }
    __syncthreads();

    // ---- phase A compute: thread (tx, p0=ty) does pairs p0, p0+16 ----
    {
        ull acc0 = 0ull, acc1 = 0ull;
        #pragma unroll 8
        for (int k = 0; k < NODE_DIM; k++) {
            unsigned xu = __float_as_uint(u.A.Xs[tx][k]);
            ull x2;
            asm("mov.b64 %0, {%1, %2};" : "=l"(x2) : "r"(xu), "r"(xu));
            ull w0 = u.A.We[k][ty];
            ull w1 = u.A.We[k][ty + 16];
            asm("fma.rn.f32x2 %0, %1, %2, %0;" : "+l"(acc0) : "l"(x2), "l"(w0));
            asm("fma.rn.f32x2 %0, %1, %2, %0;" : "+l"(acc1) : "l"(x2), "l"(w1));
        }
        #pragma unroll
        for (int v = 0; v < 2; v++) {
            const int p = ty + 16 * v;
            ull a = v ? acc1 : acc0;
            asm("add.rn.f32x2 %0, %0, %1;" : "+l"(a) : "l"(bes[p]));
            unsigned lo_u, hi_u;
            asm("mov.b64 {%0, %1}, %2;" : "=r"(lo_u), "=r"(hi_u) : "l"(a));
            Hs[tx][2 * p]     = __uint_as_float(lo_u);
            Hs[tx][2 * p + 1] = __uint_as_float(hi_u);
        }
    }
    __syncthreads();     // Hs complete; phase A buffers now dead

    // ---- phase B fill: W1 over the union ----
    for (int idx = t; idx < 128 * 32; idx += 256) {
        int k = idx >> 5, p = idx & 31;
        u.W1s[k][p] = *(const ull*)&W1[k * HIDDEN + 2 * p];
    }
    __syncthreads();

    // ---- phase B compute: thread (tx, ty) does 4 pair-chains ----
    ull acc[4];
    #pragma unroll
    for (int v = 0; v < 4; v++) acc[v] = 0ull;

    #pragma unroll 8
    for (int k = 0; k < HIDDEN; k++) {
        unsigned xu = __float_as_uint(Hs[tx][k]);
        ull x2;
        asm("mov.b64 %0, {%1, %2};" : "=l"(x2) : "r"(xu), "r"(xu));
        ull wa0 = u.W1s[k][ty];
        ull wa1 = u.W1s[k][ty + 16];
        ull wb0 = u.W1s[64 + k][ty];
        ull wb1 = u.W1s[64 + k][ty + 16];
        asm("fma.rn.f32x2 %0, %1, %2, %0;" : "+l"(acc[0]) : "l"(x2), "l"(wa0));
        asm("fma.rn.f32x2 %0, %1, %2, %0;" : "+l"(acc[1]) : "l"(x2), "l"(wa1));
        asm("fma.rn.f32x2 %0, %1, %2, %0;" : "+l"(acc[2]) : "l"(x2), "l"(wb0));
        asm("fma.rn.f32x2 %0, %1, %2, %0;" : "+l"(acc[3]) : "l"(x2), "l"(wb1));
    }

    float pA = 0.f, pB = 0.f;
    const int node = n0 + tx;
    #pragma unroll
    for (int v = 0; v < 4; v++) {
        const int pl = (v & 1) ? ty + 16 : ty;       // pair index within half
        const int h0 = 2 * pl, h1 = 2 * pl + 1;      // original channels
        ull w = acc[v];
        if (v < 2)
            asm("add.rn.f32x2 %0, %0, %1;" : "+l"(w) : "l"(b1s[pl]));
        unsigned lo_u, hi_u;
        asm("mov.b64 {%0, %1}, %2;" : "=r"(lo_u), "=r"(hi_u) : "l"(w));
        float vx = __uint_as_float(lo_u), vy = __uint_as_float(hi_u);
        // separable sum uses signed c/2 with UNSCALED values
        float contrib = vx * c2s[h0] + vy * c2s[h1];
        if (v < 2) pA += contrib; else pB += contrib;
        // scatter-store pre-scaled by |c|/2 into sign-permuted slots
        float* dst = (v < 2) ? g_AT : g_BT;
        const int s0 = sml[h0], s1 = sml[h1];
        dst[((s0 >> 1) * N_NODES + node) * 2 + (s0 & 1)] = vx * cab[h0];
        dst[((s1 >> 1) * N_NODES + node) * 2 + (s1 & 1)] = vy * cab[h1];
    }
    pa[ty][tx] = pA;
    pb[ty][tx] = pB;
    __syncthreads();

    if (t < 16) {
        float s = __ldg(b2);
        #pragma unroll
        for (int q = 0; q < 16; q++) s += pa[q][t];
        g_Sa[n0 + t] = s;
    } else if (t < 32) {
        float s = 0.f;
        #pragma unroll
        for (int q = 0; q < 16; q++) s += pb[q][t - 16];
        g_Sb[n0 + t - 16] = s;
    }
}

// ---------------------------------------------------------------------------
// Pairwise inner step for one channel-pair row. MODE 0: both c>=0 (acc += |s|,
// and.b64 imm). MODE 1: both c<0 (acc += -|s|, or.b64 imm). MODE 2: mixed
// boundary pair (lo positive, hi negative — guaranteed by the sign sort).
// All ops in-place on aligned b64 pairs with IMMEDIATE operands.
// ---------------------------------------------------------------------------
template<int MODE>
__device__ __forceinline__ void do_hh(const ull* __restrict__ Arow,
                                      const ull* __restrict__ Brow,
                                      int ty, int tx, ull (&acc)[4][4])
{
    ull av[4], bv[4];
    #pragma unroll
    for (int r = 0; r < 4; r++) av[r] = Arow[ty + 16 * r];
    #pragma unroll
    for (int c = 0; c < 4; c++) bv[c] = Brow[tx + 16 * c];
    #pragma unroll
    for (int r = 0; r < 4; r++) {
        #pragma unroll
        for (int c = 0; c < 4; c++) {
            if (MODE == 0) {
                asm("{\n\t.reg .b64 s;\n\t"
                    "add.rn.f32x2 s, %1, %2;\n\t"
                    "and.b64 s, s, 0x7FFFFFFF7FFFFFFF;\n\t"
                    "add.rn.f32x2 %0, %0, s;\n\t}"
                    : "+l"(acc[r][c]) : "l"(av[r]), "l"(bv[c]));
            } else if (MODE == 1) {
                asm("{\n\t.reg .b64 s;\n\t"
                    "add.rn.f32x2 s, %1, %2;\n\t"
                    "or.b64 s, s, 0x8000000080000000;\n\t"
                    "add.rn.f32x2 %0, %0, s;\n\t}"
                    : "+l"(acc[r][c]) : "l"(av[r]), "l"(bv[c]));
            } else {
                asm("{\n\t.reg .b64 s;\n\t.reg .b32 lo, hi;\n\t"
                    "add.rn.f32x2 s, %1, %2;\n\t"
                    "mov.b64 {lo, hi}, s;\n\t"
                    "and.b32 lo, lo, 0x7FFFFFFF;\n\t"
                    "or.b32 hi, hi, 0x80000000;\n\t"
                    "mov.b64 s, {lo, hi};\n\t"
                    "add.rn.f32x2 %0, %0, s;\n\t}"
                    : "+l"(acc[r][c]) : "l"(av[r]), "l"(bv[c]));
            }
        }
    }
}

// ---------------------------------------------------------------------------
// Main: logit_ij = Sa_i + Sb_j + sum_pos |s'| - sum_neg |s'|, out=sigmoid, diag=0
// (s' pre-scaled by |c_h|/2; channels sign-sorted so sign handling is by
// immediate AND/OR — no mask registers, no multiply in the hot loop)
// 64x64 tile, 256 threads, 4x4 micro-tile, smem [pair][node] stride 65.
// ---------------------------------------------------------------------------
__global__ __launch_bounds__(256, 3) void pairwise(float* __restrict__ out)
{
    __shared__ ull  As[32 * 65];     // [pair][i], 16.6 KB
    __shared__ ull  Bs[32 * 65];
    __shared__ float sSa[64], sSb[64];

    const int t  = threadIdx.x;
    const int i0 = blockIdx.y * 64;
    const int j0 = blockIdx.x * 64;

    const int PB = g_PB;
    const int MX = g_MX;

    for (int idx = t; idx < 2048; idx += 256) {
        int hh = idx >> 6, col = idx & 63;
        As[hh * 65 + col] = ((const ull*)g_AT)[hh * N_NODES + i0 + col];
        Bs[hh * 65 + col] = ((const ull*)g_BT)[hh * N_NODES + j0 + col];
    }
    if (t < 64)        sSa[t]      = g_Sa[i0 + t];
    else if (t < 128)  sSb[t - 64] = g_Sb[j0 + t - 64];
    __syncthreads();

    const int tx = t & 15;      // j = j0 + tx + 16c
    const int ty = t >> 4;      // i = i0 + ty + 16r

    ull acc[4][4];
    #pragma unroll
    for (int r = 0; r < 4; r++)
        #pragma unroll
        for (int c = 0; c < 4; c++) acc[r][c] = 0ull;

    // positive pairs
    #pragma unroll 4
    for (int hh = 0; hh < PB; hh++)
        do_hh<0>(As + hh * 65, Bs + hh * 65, ty, tx, acc);
    // mixed boundary pair (at most one)
    if (MX)
        do_hh<2>(As + PB * 65, Bs + PB * 65, ty, tx, acc);
    // negative pairs
    #pragma unroll 4
    for (int hh = PB + MX; hh < 32; hh++)
        do_hh<1>(As + hh * 65, Bs + hh * 65, ty, tx, acc);

    float Sar[4], Sbc[4];
    #pragma unroll
    for (int r = 0; r < 4; r++) Sar[r] = sSa[ty + 16 * r];
    #pragma unroll
    for (int c = 0; c < 4; c++) Sbc[c] = sSb[tx + 16 * c];

    const bool dd = (i0 == j0) && (tx == ty);

    #pragma unroll
    for (int r = 0; r < 4; r++) {
        float* prow = out + (size_t)(i0 + ty + 16 * r) * N_NODES + j0 + tx;
        #pragma unroll
        for (int c = 0; c < 4; c++) {
            unsigned lo_u, hi_u;
            asm("mov.b64 {%0, %1}, %2;" : "=r"(lo_u), "=r"(hi_u) : "l"(acc[r][c]));
            float x = (__uint_as_float(lo_u) + __uint_as_float(hi_u)) + (Sar[r] + Sbc[c]);
            float e, T;
            asm("ex2.approx.f32 %0, %1;" : "=f"(e) : "f"(x * -1.4426950408889634f));
            asm("rcp.approx.f32 %0, %1;" : "=f"(T) : "f"(1.0f + e));
            if (r == c && dd) T = 0.0f;
            prow[16 * c] = T;
        }
    }
}

extern "C" void kernel_launch(void* const* d_in, const int* in_sizes, int n_in,
                              void* d_out, int out_size)
{
    const float* X     = (const float*)d_in[0];
    const float* W_enc = (const float*)d_in[1];
    const float* b_enc = (const float*)d_in[2];
    const float* W1    = (const float*)d_in[3];
    const float* b1    = (const float*)d_in[4];
    const float* W2    = (const float*)d_in[5];
    const float* b2    = (const float*)d_in[6];
    float* out = (float*)d_out;

    setup<<<1, 64>>>(W2);
    prep<<<128, 256>>>(X, W_enc, b_enc, W1, b1, W2, b2);
    dim3 grid(N_NODES / 64, N_NODES / 64);
    pairwise<<<grid, 256>>>(out);
}

// round 15
// speedup vs baseline: 1.0256x; 1.0256x over previous
#include <cuda_runtime.h>

typedef unsigned long long ull;

#define N_NODES 2048
#define NODE_DIM 128
#define HIDDEN 64

// Scratch (no allocation allowed — device globals)
// Channel-permuted, pre-scaled staging: slot s holds channel h with slotofh[h]=s,
// value scaled by |c_h|/2. Slots 0..P-1 = positive c, P..63 = negative c.
// Layout: float[(slot>>1)][node][slot&1]  -> loads as ull pairs [pair][node].
__device__ __align__(16) float g_AT[32 * N_NODES * 2];
__device__ __align__(16) float g_BT[32 * N_NODES * 2];
__device__ __align__(16) float g_Sa[N_NODES];            // b2 + sum_h (c/2) a_ih
__device__ __align__(16) float g_Sb[N_NODES];            // sum_h (c/2) b_jh
__device__ int g_slotofh[64];
__device__ int g_PB;     // number of pure-positive pairs
__device__ int g_MX;     // 1 if a mixed boundary pair exists (P odd)

// ---------------------------------------------------------------------------
// Setup: sign-sort channel permutation. 64 threads: parallel flag load,
// thread 0 serial prefix scan over smem (64 iters, trivial).
// ---------------------------------------------------------------------------
__global__ void setup(const float* __restrict__ W2)
{
    __shared__ int pos[64];
    const int t = threadIdx.x;
    if (t < 64) pos[t] = (W2[t] >= 0.0f) ? 1 : 0;
    __syncthreads();
    if (t == 0) {
        int P = 0;
        for (int h = 0; h < 64; h++) P += pos[h];
        int ip = 0, in = P;
        for (int h = 0; h < 64; h++)
            g_slotofh[h] = pos[h] ? ip++ : in++;
        g_PB = P >> 1;
        g_MX = P & 1;
    }
}

// ---------------------------------------------------------------------------
// Fused prep: per block of 16 nodes:
//   phase A: H = X @ W_enc + b_enc           (into smem Hs)
//   phase B: [a|b] = H @ [Wa|Wb] (+b1 on a), scale each channel by |c_h|/2,
//            scatter-store into sign-permuted slots of g_AT/g_BT;
//            Sa/Sb separable sums via smem reduce.
// ---------------------------------------------------------------------------
__global__ __launch_bounds__(256, 2) void prep(const float* __restrict__ X,
                                               const float* __restrict__ W_enc,
                                               const float* __restrict__ b_enc,
                                               const float* __restrict__ W1,
                                               const float* __restrict__ b1,
                                               const float* __restrict__ W2,
                                               const float* __restrict__ b2)
{
    __shared__ union {
        struct {
            float Xs[16][129];          // stride 129 -> conflict-free
            ull   We[NODE_DIM][32];     // W_enc col-pairs
        } A;
        ull W1s[128][32];               // phase B: full W1 as col-pairs
    } u;
    __shared__ float Hs[16][65];        // H tile, stride 65
    __shared__ ull   bes[32];           // b_enc pairs
    __shared__ ull   b1s[32];           // b1 pairs
    __shared__ float c2s[64];           // c/2 (signed)
    __shared__ float cab[64];           // |c|/2 per channel
    __shared__ int   sml[64];           // slotofh
    __shared__ float pa[16][17], pb[16][17];

    const int t  = threadIdx.x;
    const int n0 = blockIdx.x * 16;
    const int tx = t & 15;              // node lane
    const int ty = t >> 4;              // 0..15

    // ---- phase A fills ----
    for (int idx = t; idx < NODE_DIM * 32; idx += 256) {
        int k = idx >> 5, p = idx & 31;
        u.A.We[k][p] = *(const ull*)&W_enc[k * HIDDEN + 2 * p];
    }
    for (int idx = t; idx < 16 * NODE_DIM; idx += 256) {
        int n = idx >> 7, d = idx & 127;
        u.A.Xs[n][d] = X[(n0 + n) * NODE_DIM + d];
    }
    if (t < 32) bes[t] = *(const ull*)&b_enc[2 * t];
    else if (t >= 64 && t < 96) b1s[t - 64] = *(const ull*)&b1[2 * (t - 64)];
    if (t >= 128 && t < 192) {
        int h = t - 128;
        float w = W2[h];
        c2s[h] = 0.5f * w;
        cab[h] = 0.5f * fabsf(w);
        sml[h] = g_slotofh[h];
    }
    __syncthreads();

    // ---- phase A compute: thread (tx, p0=ty) does pairs p0, p0+16 ----
    {
        ull acc0 = 0ull, acc1 = 0ull;
        #pragma unroll 8
        for (int k = 0; k < NODE_DIM; k++) {
            unsigned xu = __float_as_uint(u.A.Xs[tx][k]);
            ull x2;
            asm("mov.b64 %0, {%1, %2};" : "=l"(x2) : "r"(xu), "r"(xu));
            ull w0 = u.A.We[k][ty];
            ull w1 = u.A.We[k][ty + 16];
            asm("fma.rn.f32x2 %0, %1, %2, %0;" : "+l"(acc0) : "l"(x2), "l"(w0));
            asm("fma.rn.f32x2 %0, %1, %2, %0;" : "+l"(acc1) : "l"(x2), "l"(w1));
        }
        #pragma unroll
        for (int v = 0; v < 2; v++) {
            const int p = ty + 16 * v;
            ull a = v ? acc1 : acc0;
            asm("add.rn.f32x2 %0, %0, %1;" : "+l"(a) : "l"(bes[p]));
            unsigned lo_u, hi_u;
            asm("mov.b64 {%0, %1}, %2;" : "=r"(lo_u), "=r"(hi_u) : "l"(a));
            Hs[tx][2 * p]     = __uint_as_float(lo_u);
            Hs[tx][2 * p + 1] = __uint_as_float(hi_u);
        }
    }
    __syncthreads();     // Hs complete; phase A buffers now dead

    // ---- phase B fill: W1 over the union ----
    for (int idx = t; idx < 128 * 32; idx += 256) {
        int k = idx >> 5, p = idx & 31;
        u.W1s[k][p] = *(const ull*)&W1[k * HIDDEN + 2 * p];
    }
    __syncthreads();

    // ---- phase B compute: thread (tx, ty) does 4 pair-chains ----
    ull acc[4];
    #pragma unroll
    for (int v = 0; v < 4; v++) acc[v] = 0ull;

    #pragma unroll 8
    for (int k = 0; k < HIDDEN; k++) {
        unsigned xu = __float_as_uint(Hs[tx][k]);
        ull x2;
        asm("mov.b64 %0, {%1, %2};" : "=l"(x2) : "r"(xu), "r"(xu));
        ull wa0 = u.W1s[k][ty];
        ull wa1 = u.W1s[k][ty + 16];
        ull wb0 = u.W1s[64 + k][ty];
        ull wb1 = u.W1s[64 + k][ty + 16];
        asm("fma.rn.f32x2 %0, %1, %2, %0;" : "+l"(acc[0]) : "l"(x2), "l"(wa0));
        asm("fma.rn.f32x2 %0, %1, %2, %0;" : "+l"(acc[1]) : "l"(x2), "l"(wa1));
        asm("fma.rn.f32x2 %0, %1, %2, %0;" : "+l"(acc[2]) : "l"(x2), "l"(wb0));
        asm("fma.rn.f32x2 %0, %1, %2, %0;" : "+l"(acc[3]) : "l"(x2), "l"(wb1));
    }

    float pA = 0.f, pB = 0.f;
    const int node = n0 + tx;
    #pragma unroll
    for (int v = 0; v < 4; v++) {
        const int pl = (v & 1) ? ty + 16 : ty;       // pair index within half
        const int h0 = 2 * pl, h1 = 2 * pl + 1;      // original channels
        ull w = acc[v];
        if (v < 2)
            asm("add.rn.f32x2 %0, %0, %1;" : "+l"(w) : "l"(b1s[pl]));
        unsigned lo_u, hi_u;
        asm("mov.b64 {%0, %1}, %2;" : "=r"(lo_u), "=r"(hi_u) : "l"(w));
        float vx = __uint_as_float(lo_u), vy = __uint_as_float(hi_u);
        // separable sum uses signed c/2 with UNSCALED values
        float contrib = vx * c2s[h0] + vy * c2s[h1];
        if (v < 2) pA += contrib; else pB += contrib;
        // scatter-store pre-scaled by |c|/2 into sign-permuted slots
        float* dst = (v < 2) ? g_AT : g_BT;
        const int s0 = sml[h0], s1 = sml[h1];
        dst[((s0 >> 1) * N_NODES + node) * 2 + (s0 & 1)] = vx * cab[h0];
        dst[((s1 >> 1) * N_NODES + node) * 2 + (s1 & 1)] = vy * cab[h1];
    }
    pa[ty][tx] = pA;
    pb[ty][tx] = pB;
    __syncthreads();

    if (t < 16) {
        float s = __ldg(b2);
        #pragma unroll
        for (int q = 0; q < 16; q++) s += pa[q][t];
        g_Sa[n0 + t] = s;
    } else if (t < 32) {
        float s = 0.f;
        #pragma unroll
        for (int q = 0; q < 16; q++) s += pb[q][t - 16];
        g_Sb[n0 + t - 16] = s;
    }
}

// ---------------------------------------------------------------------------
// Pairwise inner step for one channel-pair row. MODE 0: both c>=0 (acc += |s|,
// and.b64 imm). MODE 1: both c<0 (acc += -|s|, or.b64 imm). MODE 2: mixed
// boundary pair (lo positive, hi negative — guaranteed by the sign sort).
// All ops in-place on aligned b64 pairs with IMMEDIATE operands.
// ---------------------------------------------------------------------------
template<int MODE>
__device__ __forceinline__ void do_hh(const ull* __restrict__ Arow,
                                      const ull* __restrict__ Brow,
                                      int ty, int tx, ull (&acc)[4][4])
{
    ull av[4], bv[4];
    #pragma unroll
    for (int r = 0; r < 4; r++) av[r] = Arow[ty + 16 * r];
    #pragma unroll
    for (int c = 0; c < 4; c++) bv[c] = Brow[tx + 16 * c];
    #pragma unroll
    for (int r = 0; r < 4; r++) {
        #pragma unroll
        for (int c = 0; c < 4; c++) {
            if (MODE == 0) {
                asm("{\n\t.reg .b64 s;\n\t"
                    "add.rn.f32x2 s, %1, %2;\n\t"
                    "and.b64 s, s, 0x7FFFFFFF7FFFFFFF;\n\t"
                    "add.rn.f32x2 %0, %0, s;\n\t}"
                    : "+l"(acc[r][c]) : "l"(av[r]), "l"(bv[c]));
            } else if (MODE == 1) {
                asm("{\n\t.reg .b64 s;\n\t"
                    "add.rn.f32x2 s, %1, %2;\n\t"
                    "or.b64 s, s, 0x8000000080000000;\n\t"
                    "add.rn.f32x2 %0, %0, s;\n\t}"
                    : "+l"(acc[r][c]) : "l"(av[r]), "l"(bv[c]));
            } else {
                asm("{\n\t.reg .b64 s;\n\t.reg .b32 lo, hi;\n\t"
                    "add.rn.f32x2 s, %1, %2;\n\t"
                    "mov.b64 {lo, hi}, s;\n\t"
                    "and.b32 lo, lo, 0x7FFFFFFF;\n\t"
                    "or.b32 hi, hi, 0x80000000;\n\t"
                    "mov.b64 s, {lo, hi};\n\t"
                    "add.rn.f32x2 %0, %0, s;\n\t}"
                    : "+l"(acc[r][c]) : "l"(av[r]), "l"(bv[c]));
            }
        }
    }
}

// ---------------------------------------------------------------------------
// Main: logit_ij = Sa_i + Sb_j + sum_pos |s'| - sum_neg |s'|, out=sigmoid, diag=0
// (s' pre-scaled by |c_h|/2; channels sign-sorted so sign handling is by
// immediate AND/OR — no mask registers, no multiply in the hot loop)
// 64x64 tile, 256 threads, 4x4 micro-tile, smem [pair][node] stride 65.
// ---------------------------------------------------------------------------
__global__ __launch_bounds__(256, 3) void pairwise(float* __restrict__ out)
{
    __shared__ ull  As[32 * 65];     // [pair][i], 16.6 KB
    __shared__ ull  Bs[32 * 65];
    __shared__ float sSa[64], sSb[64];

    const int t  = threadIdx.x;
    const int i0 = blockIdx.y * 64;
    const int j0 = blockIdx.x * 64;

    const int PB = g_PB;
    const int MX = g_MX;

    for (int idx = t; idx < 2048; idx += 256) {
        int hh = idx >> 6, col = idx & 63;
        As[hh * 65 + col] = ((const ull*)g_AT)[hh * N_NODES + i0 + col];
        Bs[hh * 65 + col] = ((const ull*)g_BT)[hh * N_NODES + j0 + col];
    }
    if (t < 64)        sSa[t]      = g_Sa[i0 + t];
    else if (t < 128)  sSb[t - 64] = g_Sb[j0 + t - 64];
    __syncthreads();

    const int tx = t & 15;      // j = j0 + tx + 16c
    const int ty = t >> 4;      // i = i0 + ty + 16r

    ull acc[4][4];
    #pragma unroll
    for (int r = 0; r < 4; r++)
        #pragma unroll
        for (int c = 0; c < 4; c++) acc[r][c] = 0ull;

    // positive pairs
    #pragma unroll 4
    for (int hh = 0; hh < PB; hh++)
        do_hh<0>(As + hh * 65, Bs + hh * 65, ty, tx, acc);
    // mixed boundary pair (at most one)
    if (MX)
        do_hh<2>(As + PB * 65, Bs + PB * 65, ty, tx, acc);
    // negative pairs
    #pragma unroll 4
    for (int hh = PB + MX; hh < 32; hh++)
        do_hh<1>(As + hh * 65, Bs + hh * 65, ty, tx, acc);

    float Sar[4], Sbc[4];
    #pragma unroll
    for (int r = 0; r < 4; r++) Sar[r] = sSa[ty + 16 * r];
    #pragma unroll
    for (int c = 0; c < 4; c++) Sbc[c] = sSb[tx + 16 * c];

    const bool dd = (i0 == j0) && (tx == ty);

    #pragma unroll
    for (int r = 0; r < 4; r++) {
        float* prow = out + (size_t)(i0 + ty + 16 * r) * N_NODES + j0 + tx;
        #pragma unroll
        for (int c = 0; c < 4; c++) {
            unsigned lo_u, hi_u;
            asm("mov.b64 {%0, %1}, %2;" : "=r"(lo_u), "=r"(hi_u) : "l"(acc[r][c]));
            float x = (__uint_as_float(lo_u) + __uint_as_float(hi_u)) + (Sar[r] + Sbc[c]);
            float e, T;
            asm("ex2.approx.f32 %0, %1;" : "=f"(e) : "f"(x * -1.4426950408889634f));
            asm("rcp.approx.f32 %0, %1;" : "=f"(T) : "f"(1.0f + e));
            if (r == c && dd) T = 0.0f;
            prow[16 * c] = T;
        }
    }
}

extern "C" void kernel_launch(void* const* d_in, const int* in_sizes, int n_in,
                              void* d_out, int out_size)
{
    const float* X     = (const float*)d_in[0];
    const float* W_enc = (const float*)d_in[1];
    const float* b_enc = (const float*)d_in[2];
    const float* W1    = (const float*)d_in[3];
    const float* b1    = (const float*)d_in[4];
    const float* W2    = (const float*)d_in[5];
    const float* b2    = (const float*)d_in[6];
    float* out = (float*)d_out;

    setup<<<1, 64>>>(W2);
    prep<<<128, 256>>>(X, W_enc, b_enc, W1, b1, W2, b2);
    dim3 grid(N_NODES / 64, N_NODES / 64);
    pairwise<<<grid, 256>>>(out);
}